// round 2
// baseline (speedup 1.0000x reference)
#include <cuda_runtime.h>
#include <math.h>

#define LATENT 256
#define HID 512
#define NT 16
#define MAXB 2048

// scratch (allocation-free rule: device globals)
__device__ float g_h[MAXB * HID];
__device__ float g_e1[MAXB * HID];

// ---------------------------------------------------------------------------
// Register-blocked SGEMM: C[M,N] = act(A[M,K] @ (B0 (+ B1)) + bias)
// BM=32, BN=64, BK=16, 128 threads, 4x4 microtile per thread.
// SUM_B folds the cat(h,h)@W_e1 into one pass: B = W_e1_top + W_e1_bottom.
// ---------------------------------------------------------------------------
template<bool SUM_B, bool RELU>
__global__ __launch_bounds__(128)
void gemm_tiled(const float* __restrict__ A,
                const float* __restrict__ B0,
                const float* __restrict__ B1,
                const float* __restrict__ bias,
                float* __restrict__ C,
                int M, int N, int K)
{
    constexpr int BM = 32, BN = 64, BK = 16;
    __shared__ float As[BK][BM];
    __shared__ float Bs[BK][BN];

    const int tx = threadIdx.x;
    const int rowBase = blockIdx.y * BM;
    const int colBase = blockIdx.x * BN;

    // loader indices
    const int arow = tx >> 2;          // 0..31
    const int acol = (tx & 3) << 2;    // 0,4,8,12
    const int brw  = tx >> 4;          // 0..7
    const int bcl  = (tx & 15) << 2;   // 0..60

    // compute indices
    const int tm0 = (tx >> 4) << 2;    // 0..28
    const int tn0 = (tx & 15) << 2;    // 0..60

    float acc[4][4] = {};

    for (int k0 = 0; k0 < K; k0 += BK) {
        // A tile (BMxBK), store transposed for coalesced smem reads
        float4 av = make_float4(0.f, 0.f, 0.f, 0.f);
        int gr = rowBase + arow;
        if (gr < M)
            av = *reinterpret_cast<const float4*>(A + (size_t)gr * K + k0 + acol);
        As[acol + 0][arow] = av.x;
        As[acol + 1][arow] = av.y;
        As[acol + 2][arow] = av.z;
        As[acol + 3][arow] = av.w;

        // B tile (BKxBN), two rows per thread, optional B1 add on load
        #pragma unroll
        for (int r = 0; r < 2; r++) {
            int kr = brw + r * 8;
            float4 bv = *reinterpret_cast<const float4*>(
                B0 + (size_t)(k0 + kr) * N + colBase + bcl);
            if (SUM_B) {
                float4 b1 = *reinterpret_cast<const float4*>(
                    B1 + (size_t)(k0 + kr) * N + colBase + bcl);
                bv.x += b1.x; bv.y += b1.y; bv.z += b1.z; bv.w += b1.w;
            }
            *reinterpret_cast<float4*>(&Bs[kr][bcl]) = bv;
        }
        __syncthreads();

        #pragma unroll
        for (int kk = 0; kk < BK; kk++) {
            float4 a = *reinterpret_cast<const float4*>(&As[kk][tm0]);
            float4 b = *reinterpret_cast<const float4*>(&Bs[kk][tn0]);
            float ar[4] = {a.x, a.y, a.z, a.w};
            float br[4] = {b.x, b.y, b.z, b.w};
            #pragma unroll
            for (int i = 0; i < 4; i++)
                #pragma unroll
                for (int j = 0; j < 4; j++)
                    acc[i][j] = fmaf(ar[i], br[j], acc[i][j]);
        }
        __syncthreads();
    }

    float4 bb = *reinterpret_cast<const float4*>(bias + colBase + tn0);
    float bbr[4] = {bb.x, bb.y, bb.z, bb.w};
    #pragma unroll
    for (int i = 0; i < 4; i++) {
        int r = rowBase + tm0 + i;
        if (r < M) {
            float4 v;
            float* vp = &v.x;
            #pragma unroll
            for (int j = 0; j < 4; j++) {
                float x = acc[i][j] + bbr[j];
                if (RELU) x = fmaxf(x, 0.f);
                vp[j] = x;
            }
            *reinterpret_cast<float4*>(C + (size_t)r * N + colBase + tn0) = v;
        }
    }
}

// ---------------------------------------------------------------------------
// Finalize: one block per batch row b.
//   logits[t] = h[b] . W_node[:,t] + b_node[t]      (16-wide GEMV)
//   p         = sigmoid(e1[b] . W_e2 + b_e2)
//   out[0 : B*N*16)              = logits broadcast over N
//   out[B*N*16 : B*N*16 + B*N*N) = p * strict-lower-tri mask
// ---------------------------------------------------------------------------
__global__ __launch_bounds__(256)
void finalize_kernel(const float* __restrict__ g_h_p,
                     const float* __restrict__ g_e1_p,
                     const float* __restrict__ W_node,
                     const float* __restrict__ b_node,
                     const float* __restrict__ W_e2,
                     const float* __restrict__ b_e2,
                     float* __restrict__ out,
                     int Bsz, int N, int has_edges)
{
    const int b = blockIdx.x;
    const int tid = threadIdx.x;
    __shared__ float sh_h[HID];
    __shared__ float sh_logits[NT];
    __shared__ float sred[256];
    __shared__ float sh_p;

    for (int k = tid; k < HID; k += 256) sh_h[k] = g_h_p[(size_t)b * HID + k];

    float pp = 0.f;
    for (int k = tid; k < HID; k += 256)
        pp = fmaf(g_e1_p[(size_t)b * HID + k], W_e2[k], pp);
    sred[tid] = pp;
    __syncthreads();

    // logits: each of 8 warps handles 2 node-type columns
    {
        int warp = tid >> 5, lane = tid & 31;
        int t0 = warp * 2;
        float a0 = 0.f, a1 = 0.f;
        for (int k = lane; k < HID; k += 32) {
            float hv = sh_h[k];
            a0 = fmaf(hv, W_node[k * NT + t0], a0);
            a1 = fmaf(hv, W_node[k * NT + t0 + 1], a1);
        }
        #pragma unroll
        for (int off = 16; off; off >>= 1) {
            a0 += __shfl_down_sync(0xffffffffu, a0, off);
            a1 += __shfl_down_sync(0xffffffffu, a1, off);
        }
        if (lane == 0) {
            sh_logits[t0]     = a0 + b_node[t0];
            sh_logits[t0 + 1] = a1 + b_node[t0 + 1];
        }
    }
    __syncthreads();
    #pragma unroll
    for (int s = 128; s > 0; s >>= 1) {
        if (tid < s) sred[tid] += sred[tid + s];
        __syncthreads();
    }
    if (tid == 0) sh_p = 1.f / (1.f + expf(-(sred[0] + b_e2[0])));
    __syncthreads();

    // node_logits broadcast: [b, N, 16], vectorized float4
    size_t base1 = (size_t)b * N * NT;
    float4 lg[4];
    #pragma unroll
    for (int q = 0; q < 4; q++)
        lg[q] = make_float4(sh_logits[4*q], sh_logits[4*q+1],
                            sh_logits[4*q+2], sh_logits[4*q+3]);
    {
        float4* o4 = reinterpret_cast<float4*>(out + base1);
        int n4 = N * NT / 4;
        for (int i = tid; i < n4; i += 256)
            o4[i] = lg[i & 3];
        // scalar tail if N*NT not divisible by 4 (not expected)
        for (int i = n4 * 4 + tid; i < N * NT; i += 256)
            out[base1 + i] = sh_logits[i & (NT - 1)];
    }

    // edge_probs: p on strict lower triangle (j < i), zeros elsewhere
    if (has_edges) {
        float p = sh_p;
        size_t base2 = (size_t)Bsz * N * NT + (size_t)b * N * N;
        if ((N & 3) == 0) {
            float4* e4 = reinterpret_cast<float4*>(out + base2);
            int nr4 = N >> 2;
            int tot = N * nr4;
            for (int idx = tid; idx < tot; idx += 256) {
                int i  = idx / nr4;
                int j0 = (idx - i * nr4) << 2;
                float4 v;
                v.x = (j0 + 0 < i) ? p : 0.f;
                v.y = (j0 + 1 < i) ? p : 0.f;
                v.z = (j0 + 2 < i) ? p : 0.f;
                v.w = (j0 + 3 < i) ? p : 0.f;
                e4[idx] = v;
            }
        } else {
            for (int idx = tid; idx < N * N; idx += 256) {
                int i = idx / N, j = idx - i * N;
                out[base2 + idx] = (j < i) ? p : 0.f;
            }
        }
    }
}

// ---------------------------------------------------------------------------
// Inputs (metadata order): z, num_nodes, W_z, b_z, W_node, b_node,
//                          W_e1, b_e1, W_e2, b_e2
// num_nodes sits in device memory (can't read under graph capture);
// derive N on host from out_size: per-batch = N*N + 16*N.
// ---------------------------------------------------------------------------
extern "C" void kernel_launch(void* const* d_in, const int* in_sizes, int n_in,
                              void* d_out, int out_size)
{
    const float* z      = (const float*)d_in[0];
    const float* W_z    = (const float*)d_in[2];
    const float* b_z    = (const float*)d_in[3];
    const float* W_node = (const float*)d_in[4];
    const float* b_node = (const float*)d_in[5];
    const float* W_e1   = (const float*)d_in[6];
    const float* b_e1   = (const float*)d_in[7];
    const float* W_e2   = (const float*)d_in[8];
    const float* b_e2   = (const float*)d_in[9];
    float* out = (float*)d_out;

    int Bsz = in_sizes[0] / LATENT;
    long per = (long)out_size / (long)Bsz;

    // Solve N^2 + NT*N = per; fallback to logits-only layout if no int root.
    double disc = (double)NT * NT + 4.0 * (double)per;
    int N = (int)((-(double)NT + sqrt(disc)) * 0.5 + 0.5);
    int has_edges = 1;
    if ((long)N * N + (long)NT * N != per) {
        N = (int)(per / NT);
        has_edges = 0;
    }

    float *gh = nullptr, *ge1 = nullptr;
    cudaGetSymbolAddress((void**)&gh,  g_h);
    cudaGetSymbolAddress((void**)&ge1, g_e1);

    dim3 grid(HID / 64, (Bsz + 31) / 32);

    // h = relu(z @ W_z + b_z)                       [Bsz, 512], K=256
    gemm_tiled<false, true><<<grid, 128>>>(z, W_z, nullptr, b_z, gh,
                                           Bsz, HID, LATENT);
    // e1 = relu(h @ (W_e1_top + W_e1_bot) + b_e1)   [Bsz, 512], K=512
    gemm_tiled<true, true><<<grid, 128>>>(gh, W_e1, W_e1 + (size_t)HID * HID,
                                          b_e1, ge1, Bsz, HID, HID);
    // logits + p + broadcast writes
    finalize_kernel<<<Bsz, 256>>>(gh, ge1, W_node, b_node, W_e2, b_e2,
                                  out, Bsz, N, has_edges);
}

// round 3
// speedup vs baseline: 1.0325x; 1.0325x over previous
#include <cuda_runtime.h>
#include <math.h>

#define LATENT 256
#define HID 512
#define NT 16
#define MAXB 2048

// scratch (allocation-free rule: device globals)
__device__ float g_h[MAXB * HID];
__device__ float g_e1[MAXB * HID];
__device__ float g_we1s[HID * HID];

// ---------------------------------------------------------------------------
// W_e1_sum = W_e1[0:H, :] + W_e1[H:2H, :]   (folds cat(h,h) @ W_e1)
// ---------------------------------------------------------------------------
__global__ __launch_bounds__(256)
void wsum_kernel(const float* __restrict__ W, float* __restrict__ o)
{
    int i = blockIdx.x * 256 + threadIdx.x;   // over HID*HID/4 float4s
    float4 a = reinterpret_cast<const float4*>(W)[i];
    float4 b = reinterpret_cast<const float4*>(W + (size_t)HID * HID)[i];
    a.x += b.x; a.y += b.y; a.z += b.z; a.w += b.w;
    reinterpret_cast<float4*>(o)[i] = a;
}

// ---------------------------------------------------------------------------
// Double-buffered register-blocked SGEMM:
//   C[M,N] = act(A[M,K] @ B[K,N] + bias)
// BM=32, BN=64, BK=16, 128 threads, 4x4 microtile, smem double buffer +
// register prefetch, fully unrolled k-loop.
// ---------------------------------------------------------------------------
template<bool RELU>
__global__ __launch_bounds__(128)
void gemm_db(const float* __restrict__ A,
             const float* __restrict__ B,
             const float* __restrict__ bias,
             float* __restrict__ C,
             int M, int N, int K)
{
    constexpr int BM = 32, BN = 64, BK = 16, AP = BM + 4;  // AP pad: bank spread
    __shared__ float As[2][BK][AP];
    __shared__ float Bs[2][BK][BN];

    const int tx = threadIdx.x;
    const int rowBase = blockIdx.y * BM;
    const int colBase = blockIdx.x * BN;

    // loader indices
    const int arow = tx >> 2;           // 0..31
    const int acol = (tx & 3) << 2;     // 0,4,8,12
    const int brw  = tx >> 4;           // 0..7 (rows brw, brw+8)
    const int bcl  = (tx & 15) << 2;    // 0..60

    // compute indices
    const int tm0 = (tx >> 4) << 2;     // 0..28
    const int tn0 = (tx & 15) << 2;     // 0..60

    const bool mok = (rowBase + arow) < M;
    const float* Aptr = A + (size_t)(rowBase + arow) * K + acol;
    const float* Bptr = B + (size_t)brw * N + colBase + bcl;

    float acc[4][4] = {};

    // ---- stage 0 load ----
    float4 av = make_float4(0.f, 0.f, 0.f, 0.f);
    if (mok) av = *reinterpret_cast<const float4*>(Aptr);
    float4 bv0 = *reinterpret_cast<const float4*>(Bptr);
    float4 bv1 = *reinterpret_cast<const float4*>(Bptr + (size_t)8 * N);
    As[0][acol + 0][arow] = av.x;
    As[0][acol + 1][arow] = av.y;
    As[0][acol + 2][arow] = av.z;
    As[0][acol + 3][arow] = av.w;
    *reinterpret_cast<float4*>(&Bs[0][brw][bcl])     = bv0;
    *reinterpret_cast<float4*>(&Bs[0][brw + 8][bcl]) = bv1;
    __syncthreads();

    const int nk = K / BK;
    for (int t = 0; t < nk; t++) {
        const int buf = t & 1;

        // prefetch next tile into registers (overlaps with compute below)
        if (t + 1 < nk) {
            av = make_float4(0.f, 0.f, 0.f, 0.f);
            if (mok) av = *reinterpret_cast<const float4*>(Aptr + (t + 1) * BK);
            bv0 = *reinterpret_cast<const float4*>(Bptr + (size_t)((t + 1) * BK) * N);
            bv1 = *reinterpret_cast<const float4*>(Bptr + (size_t)((t + 1) * BK + 8) * N);
        }

        #pragma unroll
        for (int kk = 0; kk < BK; kk++) {
            float4 a = *reinterpret_cast<const float4*>(&As[buf][kk][tm0]);
            float4 b = *reinterpret_cast<const float4*>(&Bs[buf][kk][tn0]);
            float ar[4] = {a.x, a.y, a.z, a.w};
            float br[4] = {b.x, b.y, b.z, b.w};
            #pragma unroll
            for (int i = 0; i < 4; i++)
                #pragma unroll
                for (int j = 0; j < 4; j++)
                    acc[i][j] = fmaf(ar[i], br[j], acc[i][j]);
        }

        // store prefetched tile into the other buffer
        if (t + 1 < nk) {
            const int nb = buf ^ 1;
            As[nb][acol + 0][arow] = av.x;
            As[nb][acol + 1][arow] = av.y;
            As[nb][acol + 2][arow] = av.z;
            As[nb][acol + 3][arow] = av.w;
            *reinterpret_cast<float4*>(&Bs[nb][brw][bcl])     = bv0;
            *reinterpret_cast<float4*>(&Bs[nb][brw + 8][bcl]) = bv1;
        }
        __syncthreads();
    }

    // epilogue
    float4 bb = *reinterpret_cast<const float4*>(bias + colBase + tn0);
    float bbr[4] = {bb.x, bb.y, bb.z, bb.w};
    #pragma unroll
    for (int i = 0; i < 4; i++) {
        int r = rowBase + tm0 + i;
        if (r < M) {
            float4 v;
            float* vp = &v.x;
            #pragma unroll
            for (int j = 0; j < 4; j++) {
                float x = acc[i][j] + bbr[j];
                if (RELU) x = fmaxf(x, 0.f);
                vp[j] = x;
            }
            *reinterpret_cast<float4*>(C + (size_t)r * N + colBase + tn0) = v;
        }
    }
}

// ---------------------------------------------------------------------------
// Finalize: one block per batch row b.
//   logits[t] = h[b] . W_node[:,t] + b_node[t]      (16-wide GEMV)
//   p         = sigmoid(e1[b] . W_e2 + b_e2)
//   out[0 : B*N*16)              = logits broadcast over N
//   out[B*N*16 : B*N*16 + B*N*N) = p * strict-lower-tri mask
// ---------------------------------------------------------------------------
__global__ __launch_bounds__(256)
void finalize_kernel(const float* __restrict__ g_h_p,
                     const float* __restrict__ g_e1_p,
                     const float* __restrict__ W_node,
                     const float* __restrict__ b_node,
                     const float* __restrict__ W_e2,
                     const float* __restrict__ b_e2,
                     float* __restrict__ out,
                     int Bsz, int N, int has_edges)
{
    const int b = blockIdx.x;
    const int tid = threadIdx.x;
    __shared__ float sh_h[HID];
    __shared__ float sh_logits[NT];
    __shared__ float sred[256];
    __shared__ float sh_p;

    for (int k = tid; k < HID; k += 256) sh_h[k] = g_h_p[(size_t)b * HID + k];

    float pp = 0.f;
    for (int k = tid; k < HID; k += 256)
        pp = fmaf(g_e1_p[(size_t)b * HID + k], W_e2[k], pp);
    sred[tid] = pp;
    __syncthreads();

    // logits: each of 8 warps handles 2 node-type columns
    {
        int warp = tid >> 5, lane = tid & 31;
        int t0 = warp * 2;
        float a0 = 0.f, a1 = 0.f;
        for (int k = lane; k < HID; k += 32) {
            float hv = sh_h[k];
            a0 = fmaf(hv, W_node[k * NT + t0], a0);
            a1 = fmaf(hv, W_node[k * NT + t0 + 1], a1);
        }
        #pragma unroll
        for (int off = 16; off; off >>= 1) {
            a0 += __shfl_down_sync(0xffffffffu, a0, off);
            a1 += __shfl_down_sync(0xffffffffu, a1, off);
        }
        if (lane == 0) {
            sh_logits[t0]     = a0 + b_node[t0];
            sh_logits[t0 + 1] = a1 + b_node[t0 + 1];
        }
    }
    __syncthreads();
    #pragma unroll
    for (int s = 128; s > 0; s >>= 1) {
        if (tid < s) sred[tid] += sred[tid + s];
        __syncthreads();
    }
    if (tid == 0) sh_p = 1.f / (1.f + expf(-(sred[0] + b_e2[0])));
    __syncthreads();

    // node_logits broadcast: [b, N, 16], vectorized float4
    size_t base1 = (size_t)b * N * NT;
    float4 lg[4];
    #pragma unroll
    for (int q = 0; q < 4; q++)
        lg[q] = make_float4(sh_logits[4*q], sh_logits[4*q+1],
                            sh_logits[4*q+2], sh_logits[4*q+3]);
    {
        float4* o4 = reinterpret_cast<float4*>(out + base1);
        int n4 = N * NT / 4;
        for (int i = tid; i < n4; i += 256)
            o4[i] = lg[i & 3];
        for (int i = n4 * 4 + tid; i < N * NT; i += 256)
            out[base1 + i] = sh_logits[i & (NT - 1)];
    }

    // edge_probs: p on strict lower triangle (j < i), zeros elsewhere
    if (has_edges) {
        float p = sh_p;
        size_t base2 = (size_t)Bsz * N * NT + (size_t)b * N * N;
        if ((N & 3) == 0) {
            float4* e4 = reinterpret_cast<float4*>(out + base2);
            int nr4 = N >> 2;
            int tot = N * nr4;
            for (int idx = tid; idx < tot; idx += 256) {
                int i  = idx / nr4;
                int j0 = (idx - i * nr4) << 2;
                float4 v;
                v.x = (j0 + 0 < i) ? p : 0.f;
                v.y = (j0 + 1 < i) ? p : 0.f;
                v.z = (j0 + 2 < i) ? p : 0.f;
                v.w = (j0 + 3 < i) ? p : 0.f;
                e4[idx] = v;
            }
        } else {
            for (int idx = tid; idx < N * N; idx += 256) {
                int i = idx / N, j = idx - i * N;
                out[base2 + idx] = (j < i) ? p : 0.f;
            }
        }
    }
}

// ---------------------------------------------------------------------------
// Inputs (metadata order): z, num_nodes, W_z, b_z, W_node, b_node,
//                          W_e1, b_e1, W_e2, b_e2
// num_nodes sits in device memory (can't read under graph capture);
// derive N on host from out_size: per-batch = N*N + 16*N.
// ---------------------------------------------------------------------------
extern "C" void kernel_launch(void* const* d_in, const int* in_sizes, int n_in,
                              void* d_out, int out_size)
{
    const float* z      = (const float*)d_in[0];
    const float* W_z    = (const float*)d_in[2];
    const float* b_z    = (const float*)d_in[3];
    const float* W_node = (const float*)d_in[4];
    const float* b_node = (const float*)d_in[5];
    const float* W_e1   = (const float*)d_in[6];
    const float* b_e1   = (const float*)d_in[7];
    const float* W_e2   = (const float*)d_in[8];
    const float* b_e2   = (const float*)d_in[9];
    float* out = (float*)d_out;

    int Bsz = in_sizes[0] / LATENT;
    long per = (long)out_size / (long)Bsz;

    // Solve N^2 + NT*N = per; fallback to logits-only layout if no int root.
    double disc = (double)NT * NT + 4.0 * (double)per;
    int N = (int)((-(double)NT + sqrt(disc)) * 0.5 + 0.5);
    int has_edges = 1;
    if ((long)N * N + (long)NT * N != per) {
        N = (int)(per / NT);
        has_edges = 0;
    }

    float *gh = nullptr, *ge1 = nullptr, *gws = nullptr;
    cudaGetSymbolAddress((void**)&gh,  g_h);
    cudaGetSymbolAddress((void**)&ge1, g_e1);
    cudaGetSymbolAddress((void**)&gws, g_we1s);

    // W_e1 half-sum (independent of gemm1; cheap)
    wsum_kernel<<<(HID * HID / 4) / 256, 256>>>(W_e1, gws);

    dim3 grid(HID / 64, (Bsz + 31) / 32);

    // h = relu(z @ W_z + b_z)                  [Bsz, 512], K=256
    gemm_db<true><<<grid, 128>>>(z, W_z, b_z, gh, Bsz, HID, LATENT);
    // e1 = relu(h @ W_e1_sum + b_e1)           [Bsz, 512], K=512
    gemm_db<true><<<grid, 128>>>(gh, gws, b_e1, ge1, Bsz, HID, HID);
    // logits + p + broadcast writes
    finalize_kernel<<<Bsz, 256>>>(gh, ge1, W_node, b_node, W_e2, b_e2,
                                  out, Bsz, N, has_edges);
}

// round 4
// speedup vs baseline: 1.1465x; 1.1105x over previous
#include <cuda_runtime.h>
#include <math.h>

#define LATENT 256
#define HID 512
#define NT 16
#define MAXB 2048

// scratch (allocation-free rule: device globals)
__device__ float g_h[MAXB * HID];
__device__ float g_e1[MAXB * HID];
__device__ float g_we1s[HID * HID];

// ---------------------------------------------------------------------------
// W_e1_sum = W_e1[0:H, :] + W_e1[H:2H, :]   (folds cat(h,h) @ W_e1)
// ---------------------------------------------------------------------------
__global__ __launch_bounds__(256)
void wsum_kernel(const float* __restrict__ W, float* __restrict__ o)
{
    int i = blockIdx.x * 256 + threadIdx.x;   // over HID*HID/4 float4s
    float4 a = reinterpret_cast<const float4*>(W)[i];
    float4 b = reinterpret_cast<const float4*>(W + (size_t)HID * HID)[i];
    a.x += b.x; a.y += b.y; a.z += b.z; a.w += b.w;
    reinterpret_cast<float4*>(o)[i] = a;
}

// ---------------------------------------------------------------------------
// Double-buffered register-blocked SGEMM:
//   C[M,N] = relu(A[M,K] @ B[K,N] + bias)
// BM=32, BN=64, BK=16, 128 threads, 4x4 microtile, smem double buffer +
// register prefetch, fully unrolled k-loop.
// ---------------------------------------------------------------------------
template<bool RELU>
__global__ __launch_bounds__(128)
void gemm_db(const float* __restrict__ A,
             const float* __restrict__ B,
             const float* __restrict__ bias,
             float* __restrict__ C,
             int M, int N, int K)
{
    constexpr int BM = 32, BN = 64, BK = 16, AP = BM + 4;
    __shared__ float As[2][BK][AP];
    __shared__ float Bs[2][BK][BN];

    const int tx = threadIdx.x;
    const int rowBase = blockIdx.y * BM;
    const int colBase = blockIdx.x * BN;

    const int arow = tx >> 2;
    const int acol = (tx & 3) << 2;
    const int brw  = tx >> 4;
    const int bcl  = (tx & 15) << 2;

    const int tm0 = (tx >> 4) << 2;
    const int tn0 = (tx & 15) << 2;

    const bool mok = (rowBase + arow) < M;
    const float* Aptr = A + (size_t)(rowBase + arow) * K + acol;
    const float* Bptr = B + (size_t)brw * N + colBase + bcl;

    float acc[4][4] = {};

    float4 av = make_float4(0.f, 0.f, 0.f, 0.f);
    if (mok) av = *reinterpret_cast<const float4*>(Aptr);
    float4 bv0 = *reinterpret_cast<const float4*>(Bptr);
    float4 bv1 = *reinterpret_cast<const float4*>(Bptr + (size_t)8 * N);
    As[0][acol + 0][arow] = av.x;
    As[0][acol + 1][arow] = av.y;
    As[0][acol + 2][arow] = av.z;
    As[0][acol + 3][arow] = av.w;
    *reinterpret_cast<float4*>(&Bs[0][brw][bcl])     = bv0;
    *reinterpret_cast<float4*>(&Bs[0][brw + 8][bcl]) = bv1;
    __syncthreads();

    const int nk = K / BK;
    for (int t = 0; t < nk; t++) {
        const int buf = t & 1;

        if (t + 1 < nk) {
            av = make_float4(0.f, 0.f, 0.f, 0.f);
            if (mok) av = *reinterpret_cast<const float4*>(Aptr + (t + 1) * BK);
            bv0 = *reinterpret_cast<const float4*>(Bptr + (size_t)((t + 1) * BK) * N);
            bv1 = *reinterpret_cast<const float4*>(Bptr + (size_t)((t + 1) * BK + 8) * N);
        }

        #pragma unroll
        for (int kk = 0; kk < BK; kk++) {
            float4 a = *reinterpret_cast<const float4*>(&As[buf][kk][tm0]);
            float4 b = *reinterpret_cast<const float4*>(&Bs[buf][kk][tn0]);
            float ar[4] = {a.x, a.y, a.z, a.w};
            float br[4] = {b.x, b.y, b.z, b.w};
            #pragma unroll
            for (int i = 0; i < 4; i++)
                #pragma unroll
                for (int j = 0; j < 4; j++)
                    acc[i][j] = fmaf(ar[i], br[j], acc[i][j]);
        }

        if (t + 1 < nk) {
            const int nb = buf ^ 1;
            As[nb][acol + 0][arow] = av.x;
            As[nb][acol + 1][arow] = av.y;
            As[nb][acol + 2][arow] = av.z;
            As[nb][acol + 3][arow] = av.w;
            *reinterpret_cast<float4*>(&Bs[nb][brw][bcl])     = bv0;
            *reinterpret_cast<float4*>(&Bs[nb][brw + 8][bcl]) = bv1;
        }
        __syncthreads();
    }

    float4 bb = *reinterpret_cast<const float4*>(bias + colBase + tn0);
    float bbr[4] = {bb.x, bb.y, bb.z, bb.w};
    #pragma unroll
    for (int i = 0; i < 4; i++) {
        int r = rowBase + tm0 + i;
        if (r < M) {
            float4 v;
            float* vp = &v.x;
            #pragma unroll
            for (int j = 0; j < 4; j++) {
                float x = acc[i][j] + bbr[j];
                if (RELU) x = fmaxf(x, 0.f);
                vp[j] = x;
            }
            *reinterpret_cast<float4*>(C + (size_t)r * N + colBase + tn0) = v;
        }
    }
}

// ---------------------------------------------------------------------------
// Finalize: one block per batch row b. Division-free, no local-memory arrays.
//   logits[t] = h[b] . W_node[:,t] + b_node[t]
//   p         = sigmoid(e1[b] . W_e2 + b_e2)
//   out[0 : B*N*16)              = logits broadcast over N
//   out[B*N*16 : B*N*16 + B*N*N) = p * strict-lower-tri mask
// ---------------------------------------------------------------------------
__global__ __launch_bounds__(256)
void finalize_kernel(const float* __restrict__ g_h_p,
                     const float* __restrict__ g_e1_p,
                     const float* __restrict__ W_node,
                     const float* __restrict__ b_node,
                     const float* __restrict__ W_e2,
                     const float* __restrict__ b_e2,
                     float* __restrict__ out,
                     int Bsz, int N, int has_edges)
{
    const int b = blockIdx.x;
    const int tid = threadIdx.x;
    const int warp = tid >> 5, lane = tid & 31;
    __shared__ float sh_h[HID];
    __shared__ float sh_logits[NT];
    __shared__ float swarp[8];
    __shared__ float sh_p;

    for (int k = tid; k < HID; k += 256) sh_h[k] = g_h_p[(size_t)b * HID + k];

    // p partial dot (warp-shuffle reduce)
    float pp = 0.f;
    for (int k = tid; k < HID; k += 256)
        pp = fmaf(g_e1_p[(size_t)b * HID + k], W_e2[k], pp);
    #pragma unroll
    for (int off = 16; off; off >>= 1)
        pp += __shfl_down_sync(0xffffffffu, pp, off);
    if (lane == 0) swarp[warp] = pp;
    __syncthreads();

    // logits: each of 8 warps handles 2 node-type columns (needs sh_h ready)
    {
        int t0 = warp * 2;
        float a0 = 0.f, a1 = 0.f;
        for (int k = lane; k < HID; k += 32) {
            float hv = sh_h[k];
            a0 = fmaf(hv, W_node[k * NT + t0], a0);
            a1 = fmaf(hv, W_node[k * NT + t0 + 1], a1);
        }
        #pragma unroll
        for (int off = 16; off; off >>= 1) {
            a0 += __shfl_down_sync(0xffffffffu, a0, off);
            a1 += __shfl_down_sync(0xffffffffu, a1, off);
        }
        if (lane == 0) {
            sh_logits[t0]     = a0 + b_node[t0];
            sh_logits[t0 + 1] = a1 + b_node[t0 + 1];
        }
    }
    if (tid == 0) {
        float s = swarp[0] + swarp[1] + swarp[2] + swarp[3]
                + swarp[4] + swarp[5] + swarp[6] + swarp[7];
        sh_p = 1.f / (1.f + expf(-(s + b_e2[0])));
    }
    __syncthreads();

    // ---- node_logits broadcast: [b, N, 16] ----
    // float4 index i covers floats [4i, 4i+4); pattern period = 4 float4s.
    // Stride 256 ≡ 0 (mod 4) → (i & 3) == (tid & 3): loop-invariant smem read.
    size_t base1 = (size_t)b * N * NT;
    if (((N * NT) & 3) == 0) {
        float4 myv = *reinterpret_cast<const float4*>(&sh_logits[(tid & 3) << 2]);
        float4* o4 = reinterpret_cast<float4*>(out + base1);
        int n4 = (N * NT) >> 2;
        for (int i = tid; i < n4; i += 256)
            o4[i] = myv;
    } else {
        for (int i = tid; i < N * NT; i += 256)
            out[base1 + i] = sh_logits[i & (NT - 1)];
    }

    // ---- edge_probs: warp-per-row, division-free ----
    if (has_edges) {
        float p = sh_p;
        size_t base2 = (size_t)Bsz * N * NT + (size_t)b * N * N;
        if ((N & 3) == 0) {
            float4* e4 = reinterpret_cast<float4*>(out + base2);
            const int nr4 = N >> 2;
            for (int i = warp; i < N; i += 8) {
                float4* row = e4 + (size_t)i * nr4;
                for (int c = lane; c < nr4; c += 32) {
                    int j0 = c << 2;
                    float4 v;
                    v.x = (j0 + 0 < i) ? p : 0.f;
                    v.y = (j0 + 1 < i) ? p : 0.f;
                    v.z = (j0 + 2 < i) ? p : 0.f;
                    v.w = (j0 + 3 < i) ? p : 0.f;
                    row[c] = v;
                }
            }
        } else {
            for (int i = warp; i < N; i += 8) {
                float* row = out + base2 + (size_t)i * N;
                for (int j = lane; j < N; j += 32)
                    row[j] = (j < i) ? p : 0.f;
            }
        }
    }
}

// ---------------------------------------------------------------------------
// Inputs (metadata order): z, num_nodes, W_z, b_z, W_node, b_node,
//                          W_e1, b_e1, W_e2, b_e2
// num_nodes sits in device memory (can't read under graph capture);
// derive N on host from out_size: per-batch = N*N + 16*N.
// ---------------------------------------------------------------------------
extern "C" void kernel_launch(void* const* d_in, const int* in_sizes, int n_in,
                              void* d_out, int out_size)
{
    const float* z      = (const float*)d_in[0];
    const float* W_z    = (const float*)d_in[2];
    const float* b_z    = (const float*)d_in[3];
    const float* W_node = (const float*)d_in[4];
    const float* b_node = (const float*)d_in[5];
    const float* W_e1   = (const float*)d_in[6];
    const float* b_e1   = (const float*)d_in[7];
    const float* W_e2   = (const float*)d_in[8];
    const float* b_e2   = (const float*)d_in[9];
    float* out = (float*)d_out;

    int Bsz = in_sizes[0] / LATENT;
    long per = (long)out_size / (long)Bsz;

    double disc = (double)NT * NT + 4.0 * (double)per;
    int N = (int)((-(double)NT + sqrt(disc)) * 0.5 + 0.5);
    int has_edges = 1;
    if ((long)N * N + (long)NT * N != per) {
        N = (int)(per / NT);
        has_edges = 0;
    }

    float *gh = nullptr, *ge1 = nullptr, *gws = nullptr;
    cudaGetSymbolAddress((void**)&gh,  g_h);
    cudaGetSymbolAddress((void**)&ge1, g_e1);
    cudaGetSymbolAddress((void**)&gws, g_we1s);

    wsum_kernel<<<(HID * HID / 4) / 256, 256>>>(W_e1, gws);

    dim3 grid(HID / 64, (Bsz + 31) / 32);

    gemm_db<true><<<grid, 128>>>(z, W_z, b_z, gh, Bsz, HID, LATENT);
    gemm_db<true><<<grid, 128>>>(gh, gws, b_e1, ge1, Bsz, HID, HID);
    finalize_kernel<<<Bsz, 256>>>(gh, ge1, W_node, b_node, W_e2, b_e2,
                                  out, Bsz, N, has_edges);
}

// round 5
// speedup vs baseline: 1.2516x; 1.0917x over previous
#include <cuda_runtime.h>
#include <math.h>

#define LATENT 256
#define HID 512
#define NT 16
#define MAXB 2048

// scratch (allocation-free rule: device globals)
__device__ float g_h[MAXB * HID];
__device__ float g_e1[MAXB * HID];
__device__ float g_we1s[HID * HID];
__device__ float g_small[MAXB * 32];   // per batch: logits[0..15], p at [16]

// ---------------------------------------------------------------------------
// W_e1_sum = W_e1[0:H, :] + W_e1[H:2H, :]   (folds cat(h,h) @ W_e1)
// ---------------------------------------------------------------------------
__global__ __launch_bounds__(256)
void wsum_kernel(const float* __restrict__ W, float* __restrict__ o)
{
    int i = blockIdx.x * 256 + threadIdx.x;
    float4 a = reinterpret_cast<const float4*>(W)[i];
    float4 b = reinterpret_cast<const float4*>(W + (size_t)HID * HID)[i];
    a.x += b.x; a.y += b.y; a.z += b.z; a.w += b.w;
    reinterpret_cast<float4*>(o)[i] = a;
}

// ---------------------------------------------------------------------------
// Double-buffered register-blocked SGEMM:
//   C[M,N] = relu(A[M,K] @ B[K,N] + bias)
// ---------------------------------------------------------------------------
template<bool RELU>
__global__ __launch_bounds__(128)
void gemm_db(const float* __restrict__ A,
             const float* __restrict__ B,
             const float* __restrict__ bias,
             float* __restrict__ C,
             int M, int N, int K)
{
    constexpr int BM = 32, BN = 64, BK = 16, AP = BM + 4;
    __shared__ float As[2][BK][AP];
    __shared__ float Bs[2][BK][BN];

    const int tx = threadIdx.x;
    const int rowBase = blockIdx.y * BM;
    const int colBase = blockIdx.x * BN;

    const int arow = tx >> 2;
    const int acol = (tx & 3) << 2;
    const int brw  = tx >> 4;
    const int bcl  = (tx & 15) << 2;

    const int tm0 = (tx >> 4) << 2;
    const int tn0 = (tx & 15) << 2;

    const bool mok = (rowBase + arow) < M;
    const float* Aptr = A + (size_t)(rowBase + arow) * K + acol;
    const float* Bptr = B + (size_t)brw * N + colBase + bcl;

    float acc[4][4] = {};

    float4 av = make_float4(0.f, 0.f, 0.f, 0.f);
    if (mok) av = *reinterpret_cast<const float4*>(Aptr);
    float4 bv0 = *reinterpret_cast<const float4*>(Bptr);
    float4 bv1 = *reinterpret_cast<const float4*>(Bptr + (size_t)8 * N);
    As[0][acol + 0][arow] = av.x;
    As[0][acol + 1][arow] = av.y;
    As[0][acol + 2][arow] = av.z;
    As[0][acol + 3][arow] = av.w;
    *reinterpret_cast<float4*>(&Bs[0][brw][bcl])     = bv0;
    *reinterpret_cast<float4*>(&Bs[0][brw + 8][bcl]) = bv1;
    __syncthreads();

    const int nk = K / BK;
    for (int t = 0; t < nk; t++) {
        const int buf = t & 1;

        if (t + 1 < nk) {
            av = make_float4(0.f, 0.f, 0.f, 0.f);
            if (mok) av = *reinterpret_cast<const float4*>(Aptr + (t + 1) * BK);
            bv0 = *reinterpret_cast<const float4*>(Bptr + (size_t)((t + 1) * BK) * N);
            bv1 = *reinterpret_cast<const float4*>(Bptr + (size_t)((t + 1) * BK + 8) * N);
        }

        #pragma unroll
        for (int kk = 0; kk < BK; kk++) {
            float4 a = *reinterpret_cast<const float4*>(&As[buf][kk][tm0]);
            float4 b = *reinterpret_cast<const float4*>(&Bs[buf][kk][tn0]);
            float ar[4] = {a.x, a.y, a.z, a.w};
            float br[4] = {b.x, b.y, b.z, b.w};
            #pragma unroll
            for (int i = 0; i < 4; i++)
                #pragma unroll
                for (int j = 0; j < 4; j++)
                    acc[i][j] = fmaf(ar[i], br[j], acc[i][j]);
        }

        if (t + 1 < nk) {
            const int nb = buf ^ 1;
            As[nb][acol + 0][arow] = av.x;
            As[nb][acol + 1][arow] = av.y;
            As[nb][acol + 2][arow] = av.z;
            As[nb][acol + 3][arow] = av.w;
            *reinterpret_cast<float4*>(&Bs[nb][brw][bcl])     = bv0;
            *reinterpret_cast<float4*>(&Bs[nb][brw + 8][bcl]) = bv1;
        }
        __syncthreads();
    }

    float4 bb = *reinterpret_cast<const float4*>(bias + colBase + tn0);
    float bbr[4] = {bb.x, bb.y, bb.z, bb.w};
    #pragma unroll
    for (int i = 0; i < 4; i++) {
        int r = rowBase + tm0 + i;
        if (r < M) {
            float4 v;
            float* vp = &v.x;
            #pragma unroll
            for (int j = 0; j < 4; j++) {
                float x = acc[i][j] + bbr[j];
                if (RELU) x = fmaxf(x, 0.f);
                vp[j] = x;
            }
            *reinterpret_cast<float4*>(C + (size_t)r * N + colBase + tn0) = v;
        }
    }
}

// ---------------------------------------------------------------------------
// head_kernel: one block per batch b. Coalesced W_node access.
//   logits[t] = h[b] . W_node[:,t] + b_node[t]   -> g_small[b*32 + t]
//   p = sigmoid(e1[b] . W_e2 + b_e2)             -> g_small[b*32 + 16]
// W_node read flat: float4 j covers row k=j>>2, cols (j&3)*4..+3.
// With stride 256, (j&3) == (tid&3) is loop-invariant -> fixed col group.
// ---------------------------------------------------------------------------
__global__ __launch_bounds__(256)
void head_kernel(const float* __restrict__ g_h_p,
                 const float* __restrict__ g_e1_p,
                 const float* __restrict__ W_node,
                 const float* __restrict__ b_node,
                 const float* __restrict__ W_e2,
                 const float* __restrict__ b_e2,
                 float* __restrict__ sm)
{
    const int b = blockIdx.x;
    const int tid = threadIdx.x;
    const int warp = tid >> 5, lane = tid & 31;
    __shared__ float sh_h[HID];
    __shared__ float swarp[8];
    __shared__ float sacc[8][4][4];   // [warp][lane<4][col]

    // load h row into smem (float2-coalesced)
    {
        const float2* hp = reinterpret_cast<const float2*>(g_h_p + (size_t)b * HID);
        reinterpret_cast<float2*>(sh_h)[tid] = hp[tid];
    }

    // p partial dot over e1 row
    float pp = 0.f;
    {
        const float2* ep = reinterpret_cast<const float2*>(g_e1_p + (size_t)b * HID);
        const float2* wp = reinterpret_cast<const float2*>(W_e2);
        float2 e = ep[tid];
        float2 w = wp[tid];
        pp = fmaf(e.x, w.x, e.y * w.y);
    }
    #pragma unroll
    for (int off = 16; off; off >>= 1)
        pp += __shfl_down_sync(0xffffffffu, pp, off);
    if (lane == 0) swarp[warp] = pp;
    __syncthreads();

    // logits: flat-coalesced W_node float4 loads
    const float4* W4 = reinterpret_cast<const float4*>(W_node);
    float a0 = 0.f, a1 = 0.f, a2 = 0.f, a3 = 0.f;
    #pragma unroll
    for (int i = 0; i < (HID * NT / 4) / 256; i++) {
        int j = tid + i * 256;
        float hv = sh_h[j >> 2];
        float4 w = W4[j];
        a0 = fmaf(hv, w.x, a0);
        a1 = fmaf(hv, w.y, a1);
        a2 = fmaf(hv, w.z, a2);
        a3 = fmaf(hv, w.w, a3);
    }
    // reduce lanes with same (lane & 3)
    #pragma unroll
    for (int off = 16; off >= 4; off >>= 1) {
        a0 += __shfl_down_sync(0xffffffffu, a0, off);
        a1 += __shfl_down_sync(0xffffffffu, a1, off);
        a2 += __shfl_down_sync(0xffffffffu, a2, off);
        a3 += __shfl_down_sync(0xffffffffu, a3, off);
    }
    if (lane < 4) {
        sacc[warp][lane][0] = a0;
        sacc[warp][lane][1] = a1;
        sacc[warp][lane][2] = a2;
        sacc[warp][lane][3] = a3;
    }
    __syncthreads();

    if (tid < NT) {
        // t = (group g = tid>>2)*4 + (col c = tid&3)
        float s = 0.f;
        #pragma unroll
        for (int w = 0; w < 8; w++)
            s += sacc[w][tid >> 2][tid & 3];
        sm[(size_t)b * 32 + tid] = s + b_node[tid];
    }
    if (tid == 224) {  // a different warp than tid<16 work
        float s = swarp[0] + swarp[1] + swarp[2] + swarp[3]
                + swarp[4] + swarp[5] + swarp[6] + swarp[7];
        sm[(size_t)b * 32 + 16] = 1.f / (1.f + expf(-(s + b_e2[0])));
    }
}

// ---------------------------------------------------------------------------
// write_kernel: one block per batch. Pure store stream, no syncs.
//   out[0 : B*N*16)  = logits broadcast over N
//   out[B*N*16 : ..] = p on strict lower triangle (j < i), else 0
// ---------------------------------------------------------------------------
__global__ __launch_bounds__(256)
void write_kernel(const float* __restrict__ sm,
                  float* __restrict__ out,
                  int Bsz, int N, int has_edges)
{
    const int b = blockIdx.x;
    const int tid = threadIdx.x;
    const int warp = tid >> 5, lane = tid & 31;
    const float* ls = sm + (size_t)b * 32;

    size_t base1 = (size_t)b * N * NT;
    if (((N * NT) & 3) == 0) {
        float4 myv = reinterpret_cast<const float4*>(ls)[tid & 3];
        float4* o4 = reinterpret_cast<float4*>(out + base1);
        int n4 = (N * NT) >> 2;
        for (int i = tid; i < n4; i += 256)
            o4[i] = myv;
    } else {
        for (int i = tid; i < N * NT; i += 256)
            out[base1 + i] = ls[i & (NT - 1)];
    }

    if (has_edges) {
        float p = ls[16];
        size_t base2 = (size_t)Bsz * N * NT + (size_t)b * N * N;
        if ((N & 3) == 0) {
            float4* e4 = reinterpret_cast<float4*>(out + base2);
            const int nr4 = N >> 2;
            for (int i = warp; i < N; i += 8) {
                float4* row = e4 + (size_t)i * nr4;
                for (int c = lane; c < nr4; c += 32) {
                    int j0 = c << 2;
                    float4 v;
                    v.x = (j0 + 0 < i) ? p : 0.f;
                    v.y = (j0 + 1 < i) ? p : 0.f;
                    v.z = (j0 + 2 < i) ? p : 0.f;
                    v.w = (j0 + 3 < i) ? p : 0.f;
                    row[c] = v;
                }
            }
        } else {
            for (int i = warp; i < N; i += 8) {
                float* row = out + base2 + (size_t)i * N;
                for (int j = lane; j < N; j += 32)
                    row[j] = (j < i) ? p : 0.f;
            }
        }
    }
}

// ---------------------------------------------------------------------------
// Inputs (metadata order): z, num_nodes, W_z, b_z, W_node, b_node,
//                          W_e1, b_e1, W_e2, b_e2
// num_nodes sits in device memory; derive N on host from out_size.
// ---------------------------------------------------------------------------
extern "C" void kernel_launch(void* const* d_in, const int* in_sizes, int n_in,
                              void* d_out, int out_size)
{
    const float* z      = (const float*)d_in[0];
    const float* W_z    = (const float*)d_in[2];
    const float* b_z    = (const float*)d_in[3];
    const float* W_node = (const float*)d_in[4];
    const float* b_node = (const float*)d_in[5];
    const float* W_e1   = (const float*)d_in[6];
    const float* b_e1   = (const float*)d_in[7];
    const float* W_e2   = (const float*)d_in[8];
    const float* b_e2   = (const float*)d_in[9];
    float* out = (float*)d_out;

    int Bsz = in_sizes[0] / LATENT;
    long per = (long)out_size / (long)Bsz;

    double disc = (double)NT * NT + 4.0 * (double)per;
    int N = (int)((-(double)NT + sqrt(disc)) * 0.5 + 0.5);
    int has_edges = 1;
    if ((long)N * N + (long)NT * N != per) {
        N = (int)(per / NT);
        has_edges = 0;
    }

    float *gh = nullptr, *ge1 = nullptr, *gws = nullptr, *gsm = nullptr;
    cudaGetSymbolAddress((void**)&gh,  g_h);
    cudaGetSymbolAddress((void**)&ge1, g_e1);
    cudaGetSymbolAddress((void**)&gws, g_we1s);
    cudaGetSymbolAddress((void**)&gsm, g_small);

    wsum_kernel<<<(HID * HID / 4) / 256, 256>>>(W_e1, gws);

    dim3 grid(HID / 64, (Bsz + 31) / 32);

    gemm_db<true><<<grid, 128>>>(z, W_z, b_z, gh, Bsz, HID, LATENT);
    gemm_db<true><<<grid, 128>>>(gh, gws, b_e1, ge1, Bsz, HID, HID);
    head_kernel<<<Bsz, 256>>>(gh, ge1, W_node, b_node, W_e2, b_e2, gsm);
    write_kernel<<<Bsz, 256>>>(gsm, out, Bsz, N, has_edges);
}

// round 6
// speedup vs baseline: 1.3426x; 1.0727x over previous
#include <cuda_runtime.h>
#include <math.h>

#define LATENT 256
#define HID 512
#define NT 16
#define MAXB 2048

// scratch (allocation-free rule: device globals)
__device__ float g_h[MAXB * HID];
__device__ float g_we1s[HID * HID];
__device__ float g_small[MAXB * 32];   // per batch: logits[0..15]
__device__ float g_p[MAXB];            // per batch: pre-sigmoid accumulator

// ---------------------------------------------------------------------------
// W_e1_sum = W_e1[0:H, :] + W_e1[H:2H, :]   (folds cat(h,h) @ W_e1)
// Also zeroes g_p for this launch (graph-replay safe).
// ---------------------------------------------------------------------------
__global__ __launch_bounds__(256)
void wsum_kernel(const float* __restrict__ W, float* __restrict__ o,
                 float* __restrict__ gp, int Bsz)
{
    int i = blockIdx.x * 256 + threadIdx.x;
    float4 a = reinterpret_cast<const float4*>(W)[i];
    float4 b = reinterpret_cast<const float4*>(W + (size_t)HID * HID)[i];
    a.x += b.x; a.y += b.y; a.z += b.z; a.w += b.w;
    reinterpret_cast<float4*>(o)[i] = a;
    if (i < Bsz) gp[i] = 0.f;
}

// ---------------------------------------------------------------------------
// Double-buffered register-blocked SGEMM:
//   X = relu(A[M,K] @ B[K,N] + bias)
//   STORE_C: write X to C.
//   P_EPI:   atomicAdd per-row dot(X_row, We2[col range]) into gp[row].
// BM=32, BN=64, BK=16, 128 threads, 4x4 microtile.
// ---------------------------------------------------------------------------
template<bool RELU, bool STORE_C, bool P_EPI>
__global__ __launch_bounds__(128)
void gemm_db(const float* __restrict__ A,
             const float* __restrict__ B,
             const float* __restrict__ bias,
             float* __restrict__ C,
             const float* __restrict__ We2,
             float* __restrict__ gp,
             int M, int N, int K)
{
    constexpr int BM = 32, BN = 64, BK = 16, AP = BM + 4;
    __shared__ float As[2][BK][AP];
    __shared__ float Bs[2][BK][BN];

    const int tx = threadIdx.x;
    const int rowBase = blockIdx.y * BM;
    const int colBase = blockIdx.x * BN;

    const int arow = tx >> 2;
    const int acol = (tx & 3) << 2;
    const int brw  = tx >> 4;
    const int bcl  = (tx & 15) << 2;

    const int tm0 = (tx >> 4) << 2;
    const int tn0 = (tx & 15) << 2;

    const bool mok = (rowBase + arow) < M;
    const float* Aptr = A + (size_t)(rowBase + arow) * K + acol;
    const float* Bptr = B + (size_t)brw * N + colBase + bcl;

    float acc[4][4] = {};

    float4 av = make_float4(0.f, 0.f, 0.f, 0.f);
    if (mok) av = *reinterpret_cast<const float4*>(Aptr);
    float4 bv0 = *reinterpret_cast<const float4*>(Bptr);
    float4 bv1 = *reinterpret_cast<const float4*>(Bptr + (size_t)8 * N);
    As[0][acol + 0][arow] = av.x;
    As[0][acol + 1][arow] = av.y;
    As[0][acol + 2][arow] = av.z;
    As[0][acol + 3][arow] = av.w;
    *reinterpret_cast<float4*>(&Bs[0][brw][bcl])     = bv0;
    *reinterpret_cast<float4*>(&Bs[0][brw + 8][bcl]) = bv1;
    __syncthreads();

    const int nk = K / BK;
    for (int t = 0; t < nk; t++) {
        const int buf = t & 1;

        if (t + 1 < nk) {
            av = make_float4(0.f, 0.f, 0.f, 0.f);
            if (mok) av = *reinterpret_cast<const float4*>(Aptr + (t + 1) * BK);
            bv0 = *reinterpret_cast<const float4*>(Bptr + (size_t)((t + 1) * BK) * N);
            bv1 = *reinterpret_cast<const float4*>(Bptr + (size_t)((t + 1) * BK + 8) * N);
        }

        #pragma unroll
        for (int kk = 0; kk < BK; kk++) {
            float4 a = *reinterpret_cast<const float4*>(&As[buf][kk][tm0]);
            float4 b = *reinterpret_cast<const float4*>(&Bs[buf][kk][tn0]);
            float ar[4] = {a.x, a.y, a.z, a.w};
            float br[4] = {b.x, b.y, b.z, b.w};
            #pragma unroll
            for (int i = 0; i < 4; i++)
                #pragma unroll
                for (int j = 0; j < 4; j++)
                    acc[i][j] = fmaf(ar[i], br[j], acc[i][j]);
        }

        if (t + 1 < nk) {
            const int nb = buf ^ 1;
            As[nb][acol + 0][arow] = av.x;
            As[nb][acol + 1][arow] = av.y;
            As[nb][acol + 2][arow] = av.z;
            As[nb][acol + 3][arow] = av.w;
            *reinterpret_cast<float4*>(&Bs[nb][brw][bcl])     = bv0;
            *reinterpret_cast<float4*>(&Bs[nb][brw + 8][bcl]) = bv1;
        }
        __syncthreads();
    }

    // epilogue
    float4 bb = *reinterpret_cast<const float4*>(bias + colBase + tn0);
    float bbr[4] = {bb.x, bb.y, bb.z, bb.w};
    float4 w4;
    if (P_EPI) w4 = *reinterpret_cast<const float4*>(We2 + colBase + tn0);

    #pragma unroll
    for (int i = 0; i < 4; i++) {
        int r = rowBase + tm0 + i;
        float xr[4];
        #pragma unroll
        for (int j = 0; j < 4; j++) {
            float x = acc[i][j] + bbr[j];
            if (RELU) x = fmaxf(x, 0.f);
            xr[j] = x;
        }
        if (STORE_C && r < M) {
            float4 v = make_float4(xr[0], xr[1], xr[2], xr[3]);
            *reinterpret_cast<float4*>(C + (size_t)r * N + colBase + tn0) = v;
        }
        if (P_EPI) {
            float s = xr[0] * w4.x;
            s = fmaf(xr[1], w4.y, s);
            s = fmaf(xr[2], w4.z, s);
            s = fmaf(xr[3], w4.w, s);
            // reduce over the 16 threads sharing this row (width-16 segments)
            #pragma unroll
            for (int off = 8; off; off >>= 1)
                s += __shfl_down_sync(0xffffffffu, s, off, 16);
            if ((tx & 15) == 0 && r < M)
                atomicAdd(&gp[r], s);
        }
    }
}

// ---------------------------------------------------------------------------
// finalize: one block per batch b. Reductions then pure store stream.
//   logits[t] = h[b] . W_node[:,t] + b_node[t]   (coalesced flat W_node read)
//   p = sigmoid(g_p[b] + b_e2)
//   out[0 : B*N*16)  = logits broadcast over N
//   out[B*N*16 : ..] = p on strict lower triangle (j < i), else 0
// ---------------------------------------------------------------------------
__global__ __launch_bounds__(256)
void finalize_kernel(const float* __restrict__ g_h_p,
                     const float* __restrict__ gp,
                     const float* __restrict__ W_node,
                     const float* __restrict__ b_node,
                     const float* __restrict__ b_e2,
                     float* __restrict__ out,
                     int Bsz, int N, int has_edges)
{
    const int b = blockIdx.x;
    const int tid = threadIdx.x;
    const int warp = tid >> 5, lane = tid & 31;
    __shared__ float sh_h[HID];
    __shared__ float sh_logits[NT];
    __shared__ float sacc[8][4][4];   // [warp][lane&3][col]

    const float p = 1.f / (1.f + expf(-(gp[b] + b_e2[0])));

    // load h row into smem (float2-coalesced)
    {
        const float2* hp = reinterpret_cast<const float2*>(g_h_p + (size_t)b * HID);
        reinterpret_cast<float2*>(sh_h)[tid] = hp[tid];
    }
    __syncthreads();

    // logits: flat-coalesced W_node float4 loads
    {
        const float4* W4 = reinterpret_cast<const float4*>(W_node);
        float a0 = 0.f, a1 = 0.f, a2 = 0.f, a3 = 0.f;
        #pragma unroll
        for (int i = 0; i < (HID * NT / 4) / 256; i++) {
            int j = tid + i * 256;
            float hv = sh_h[j >> 2];
            float4 w = W4[j];
            a0 = fmaf(hv, w.x, a0);
            a1 = fmaf(hv, w.y, a1);
            a2 = fmaf(hv, w.z, a2);
            a3 = fmaf(hv, w.w, a3);
        }
        #pragma unroll
        for (int off = 16; off >= 4; off >>= 1) {
            a0 += __shfl_down_sync(0xffffffffu, a0, off);
            a1 += __shfl_down_sync(0xffffffffu, a1, off);
            a2 += __shfl_down_sync(0xffffffffu, a2, off);
            a3 += __shfl_down_sync(0xffffffffu, a3, off);
        }
        if (lane < 4) {
            sacc[warp][lane][0] = a0;
            sacc[warp][lane][1] = a1;
            sacc[warp][lane][2] = a2;
            sacc[warp][lane][3] = a3;
        }
    }
    __syncthreads();
    if (tid < NT) {
        float s = 0.f;
        #pragma unroll
        for (int w = 0; w < 8; w++)
            s += sacc[w][tid >> 2][tid & 3];
        sh_logits[tid] = s + b_node[tid];
    }
    __syncthreads();

    // node_logits broadcast: [b, N, 16]
    size_t base1 = (size_t)b * N * NT;
    if (((N * NT) & 3) == 0) {
        float4 myv = *reinterpret_cast<const float4*>(&sh_logits[(tid & 3) << 2]);
        float4* o4 = reinterpret_cast<float4*>(out + base1);
        int n4 = (N * NT) >> 2;
        for (int i = tid; i < n4; i += 256)
            o4[i] = myv;
    } else {
        for (int i = tid; i < N * NT; i += 256)
            out[base1 + i] = sh_logits[i & (NT - 1)];
    }

    // edge_probs: warp-per-row, division-free
    if (has_edges) {
        size_t base2 = (size_t)Bsz * N * NT + (size_t)b * N * N;
        if ((N & 3) == 0) {
            float4* e4 = reinterpret_cast<float4*>(out + base2);
            const int nr4 = N >> 2;
            for (int i = warp; i < N; i += 8) {
                float4* row = e4 + (size_t)i * nr4;
                for (int c = lane; c < nr4; c += 32) {
                    int j0 = c << 2;
                    float4 v;
                    v.x = (j0 + 0 < i) ? p : 0.f;
                    v.y = (j0 + 1 < i) ? p : 0.f;
                    v.z = (j0 + 2 < i) ? p : 0.f;
                    v.w = (j0 + 3 < i) ? p : 0.f;
                    row[c] = v;
                }
            }
        } else {
            for (int i = warp; i < N; i += 8) {
                float* row = out + base2 + (size_t)i * N;
                for (int j = lane; j < N; j += 32)
                    row[j] = (j < i) ? p : 0.f;
            }
        }
    }
}

// ---------------------------------------------------------------------------
// Inputs (metadata order): z, num_nodes, W_z, b_z, W_node, b_node,
//                          W_e1, b_e1, W_e2, b_e2
// num_nodes sits in device memory; derive N on host from out_size.
// ---------------------------------------------------------------------------
extern "C" void kernel_launch(void* const* d_in, const int* in_sizes, int n_in,
                              void* d_out, int out_size)
{
    const float* z      = (const float*)d_in[0];
    const float* W_z    = (const float*)d_in[2];
    const float* b_z    = (const float*)d_in[3];
    const float* W_node = (const float*)d_in[4];
    const float* b_node = (const float*)d_in[5];
    const float* W_e1   = (const float*)d_in[6];
    const float* b_e1   = (const float*)d_in[7];
    const float* W_e2   = (const float*)d_in[8];
    const float* b_e2   = (const float*)d_in[9];
    float* out = (float*)d_out;

    int Bsz = in_sizes[0] / LATENT;
    long per = (long)out_size / (long)Bsz;

    double disc = (double)NT * NT + 4.0 * (double)per;
    int N = (int)((-(double)NT + sqrt(disc)) * 0.5 + 0.5);
    int has_edges = 1;
    if ((long)N * N + (long)NT * N != per) {
        N = (int)(per / NT);
        has_edges = 0;
    }

    float *gh = nullptr, *gws = nullptr, *gsm = nullptr, *gpp = nullptr;
    cudaGetSymbolAddress((void**)&gh,  g_h);
    cudaGetSymbolAddress((void**)&gws, g_we1s);
    cudaGetSymbolAddress((void**)&gsm, g_small);
    cudaGetSymbolAddress((void**)&gpp, g_p);
    (void)gsm;

    // W_e1 half-sum + zero per-batch p accumulators
    wsum_kernel<<<(HID * HID / 4) / 256, 256>>>(W_e1, gws, gpp, Bsz);

    dim3 grid(HID / 64, (Bsz + 31) / 32);

    // h = relu(z @ W_z + b_z)          -> g_h
    gemm_db<true, true, false><<<grid, 128>>>(z, W_z, b_z, gh,
                                              nullptr, nullptr,
                                              Bsz, HID, LATENT);
    // x = relu(h @ W_e1_sum + b_e1); g_p[b] += x . W_e2   (no C store)
    gemm_db<true, false, true><<<grid, 128>>>(gh, gws, b_e1, nullptr,
                                              W_e2, gpp,
                                              Bsz, HID, HID);
    // logits + p + broadcast writes
    finalize_kernel<<<Bsz, 256>>>(gh, gpp, W_node, b_node, b_e2,
                                  out, Bsz, N, has_edges);
}

// round 7
// speedup vs baseline: 1.5096x; 1.1244x over previous
#include <cuda_runtime.h>
#include <math.h>

#define LATENT 256
#define HID 512
#define NT 16
#define MAXB 2048

// scratch (allocation-free rule: device globals)
__device__ float g_h[MAXB * HID];
__device__ float g_we1s[HID * HID];
__device__ float g_p[MAXB];            // per batch: pre-sigmoid accumulator

// ---------------------------------------------------------------------------
// W_e1_sum = W_e1[0:H, :] + W_e1[H:2H, :]; also zero g_p (graph-replay safe)
// ---------------------------------------------------------------------------
__global__ __launch_bounds__(256)
void wsum_kernel(const float* __restrict__ W, float* __restrict__ o,
                 float* __restrict__ gp, int Bsz)
{
    int i = blockIdx.x * 256 + threadIdx.x;
    float4 a = reinterpret_cast<const float4*>(W)[i];
    float4 b = reinterpret_cast<const float4*>(W + (size_t)HID * HID)[i];
    a.x += b.x; a.y += b.y; a.z += b.z; a.w += b.w;
    reinterpret_cast<float4*>(o)[i] = a;
    if (i < Bsz) gp[i] = 0.f;
}

// ---------------------------------------------------------------------------
// Double-buffered SGEMM, BM=64 BN=64 BK=16, 128 threads, 8x4 microtile.
//   X = relu(A[M,K] @ B[K,N] + bias)
//   STORE_C: write X. P_EPI: gp[row] += dot(X_row, We2) (atomic).
// ---------------------------------------------------------------------------
template<bool RELU, bool STORE_C, bool P_EPI>
__global__ __launch_bounds__(128)
void gemm64(const float* __restrict__ A,
            const float* __restrict__ B,
            const float* __restrict__ bias,
            float* __restrict__ C,
            const float* __restrict__ We2,
            float* __restrict__ gp,
            int M, int N, int K)
{
    constexpr int BM = 64, BN = 64, BK = 16, AP = BM + 4;
    __shared__ __align__(16) float As[2][BK][AP];
    __shared__ __align__(16) float Bs[2][BK][BN];

    const int tx = threadIdx.x;
    const int rowBase = blockIdx.y * BM;
    const int colBase = blockIdx.x * BN;

    // loaders: A tile 64x16 -> 2 float4/thread; B tile 16x64 -> 2 float4/thread
    const int ar = tx >> 2;            // 0..31 (rows ar, ar+32)
    const int ac = (tx & 3) << 2;      // 0,4,8,12
    const int br = tx >> 4;            // 0..7  (rows br, br+8)
    const int bc = (tx & 15) << 2;     // 0..60

    // compute: row-group rg (8 rows), col-group cg (4 cols)
    const int rg = tx >> 4;            // 0..7
    const int cg = tx & 15;            // 0..15
    const int rm0 = rg << 3;           // row offset in tile
    const int cn0 = cg << 2;           // col offset in tile

    const bool mok0 = (rowBase + ar) < M;
    const bool mok1 = (rowBase + ar + 32) < M;
    const float* Ap0 = A + (size_t)(rowBase + ar) * K + ac;
    const float* Ap1 = Ap0 + (size_t)32 * K;
    const float* Bp  = B + (size_t)br * N + colBase + bc;

    float acc[8][4] = {};

    // stage 0
    float4 av0 = make_float4(0.f,0.f,0.f,0.f), av1 = av0;
    if (mok0) av0 = *reinterpret_cast<const float4*>(Ap0);
    if (mok1) av1 = *reinterpret_cast<const float4*>(Ap1);
    float4 bv0 = *reinterpret_cast<const float4*>(Bp);
    float4 bv1 = *reinterpret_cast<const float4*>(Bp + (size_t)8 * N);
    {
        const float* a0p = &av0.x; const float* a1p = &av1.x;
        #pragma unroll
        for (int i = 0; i < 4; i++) {
            As[0][ac + i][ar]      = a0p[i];
            As[0][ac + i][ar + 32] = a1p[i];
        }
        *reinterpret_cast<float4*>(&Bs[0][br][bc])     = bv0;
        *reinterpret_cast<float4*>(&Bs[0][br + 8][bc]) = bv1;
    }
    __syncthreads();

    const int nk = K / BK;
    for (int t = 0; t < nk; t++) {
        const int buf = t & 1;

        if (t + 1 < nk) {
            av0 = make_float4(0.f,0.f,0.f,0.f); av1 = av0;
            if (mok0) av0 = *reinterpret_cast<const float4*>(Ap0 + (t + 1) * BK);
            if (mok1) av1 = *reinterpret_cast<const float4*>(Ap1 + (t + 1) * BK);
            bv0 = *reinterpret_cast<const float4*>(Bp + (size_t)((t + 1) * BK) * N);
            bv1 = *reinterpret_cast<const float4*>(Bp + (size_t)((t + 1) * BK + 8) * N);
        }

        #pragma unroll
        for (int kk = 0; kk < BK; kk++) {
            float4 a0 = *reinterpret_cast<const float4*>(&As[buf][kk][rm0]);
            float4 a1 = *reinterpret_cast<const float4*>(&As[buf][kk][rm0 + 4]);
            float4 b  = *reinterpret_cast<const float4*>(&Bs[buf][kk][cn0]);
            float arr[8] = {a0.x,a0.y,a0.z,a0.w,a1.x,a1.y,a1.z,a1.w};
            float brr[4] = {b.x,b.y,b.z,b.w};
            #pragma unroll
            for (int i = 0; i < 8; i++)
                #pragma unroll
                for (int j = 0; j < 4; j++)
                    acc[i][j] = fmaf(arr[i], brr[j], acc[i][j]);
        }

        if (t + 1 < nk) {
            const int nb = buf ^ 1;
            const float* a0p = &av0.x; const float* a1p = &av1.x;
            #pragma unroll
            for (int i = 0; i < 4; i++) {
                As[nb][ac + i][ar]      = a0p[i];
                As[nb][ac + i][ar + 32] = a1p[i];
            }
            *reinterpret_cast<float4*>(&Bs[nb][br][bc])     = bv0;
            *reinterpret_cast<float4*>(&Bs[nb][br + 8][bc]) = bv1;
        }
        __syncthreads();
    }

    // epilogue
    float4 bb = *reinterpret_cast<const float4*>(bias + colBase + cn0);
    float bbr[4] = {bb.x, bb.y, bb.z, bb.w};
    float4 w4;
    if (P_EPI) w4 = *reinterpret_cast<const float4*>(We2 + colBase + cn0);

    #pragma unroll
    for (int i = 0; i < 8; i++) {
        int r = rowBase + rm0 + i;
        float xr[4];
        #pragma unroll
        for (int j = 0; j < 4; j++) {
            float x = acc[i][j] + bbr[j];
            if (RELU) x = fmaxf(x, 0.f);
            xr[j] = x;
        }
        if (STORE_C && r < M) {
            float4 v = make_float4(xr[0], xr[1], xr[2], xr[3]);
            *reinterpret_cast<float4*>(C + (size_t)r * N + colBase + cn0) = v;
        }
        if (P_EPI) {
            float s = xr[0] * w4.x;
            s = fmaf(xr[1], w4.y, s);
            s = fmaf(xr[2], w4.z, s);
            s = fmaf(xr[3], w4.w, s);
            #pragma unroll
            for (int off = 8; off; off >>= 1)
                s += __shfl_down_sync(0xffffffffu, s, off, 16);
            if ((tx & 15) == 0 && r < M)
                atomicAdd(&gp[r], s);
        }
    }
}

// ---------------------------------------------------------------------------
// finalize: one block per batch b.
//   logits[t] = h[b] . W_node[:,t] + b_node[t]   (coalesced flat W_node read)
//   p = sigmoid(g_p[b] + b_e2)
//   out[0 : B*N*16)  = logits broadcast over N
//   out[B*N*16 : ..] = p on strict lower triangle (j < i), else 0
// Fast path for N==128: fully-unrolled 16 stores/thread, no inner loops.
// ---------------------------------------------------------------------------
__global__ __launch_bounds__(256)
void finalize_kernel(const float* __restrict__ g_h_p,
                     const float* __restrict__ gp,
                     const float* __restrict__ W_node,
                     const float* __restrict__ b_node,
                     const float* __restrict__ b_e2,
                     float* __restrict__ out,
                     int Bsz, int N, int has_edges)
{
    const int b = blockIdx.x;
    const int tid = threadIdx.x;
    const int warp = tid >> 5, lane = tid & 31;
    __shared__ float sh_h[HID];
    __shared__ float sh_logits[NT];
    __shared__ float sacc[8][4][4];

    const float p = 1.f / (1.f + expf(-(gp[b] + b_e2[0])));

    {
        const float2* hp = reinterpret_cast<const float2*>(g_h_p + (size_t)b * HID);
        reinterpret_cast<float2*>(sh_h)[tid] = hp[tid];
    }
    __syncthreads();

    // logits: flat-coalesced W_node float4 loads
    {
        const float4* W4 = reinterpret_cast<const float4*>(W_node);
        float a0 = 0.f, a1 = 0.f, a2 = 0.f, a3 = 0.f;
        #pragma unroll
        for (int i = 0; i < (HID * NT / 4) / 256; i++) {
            int j = tid + i * 256;
            float hv = sh_h[j >> 2];
            float4 w = W4[j];
            a0 = fmaf(hv, w.x, a0);
            a1 = fmaf(hv, w.y, a1);
            a2 = fmaf(hv, w.z, a2);
            a3 = fmaf(hv, w.w, a3);
        }
        #pragma unroll
        for (int off = 16; off >= 4; off >>= 1) {
            a0 += __shfl_down_sync(0xffffffffu, a0, off);
            a1 += __shfl_down_sync(0xffffffffu, a1, off);
            a2 += __shfl_down_sync(0xffffffffu, a2, off);
            a3 += __shfl_down_sync(0xffffffffu, a3, off);
        }
        if (lane < 4) {
            sacc[warp][lane][0] = a0;
            sacc[warp][lane][1] = a1;
            sacc[warp][lane][2] = a2;
            sacc[warp][lane][3] = a3;
        }
    }
    __syncthreads();
    if (tid < NT) {
        float s = 0.f;
        #pragma unroll
        for (int w = 0; w < 8; w++)
            s += sacc[w][tid >> 2][tid & 3];
        sh_logits[tid] = s + b_node[tid];
    }
    __syncthreads();

    // node_logits broadcast
    size_t base1 = (size_t)b * N * NT;
    if (((N * NT) & 3) == 0) {
        float4 myv = *reinterpret_cast<const float4*>(&sh_logits[(tid & 3) << 2]);
        float4* o4 = reinterpret_cast<float4*>(out + base1);
        int n4 = (N * NT) >> 2;
        for (int i = tid; i < n4; i += 256)
            o4[i] = myv;
    } else {
        for (int i = tid; i < N * NT; i += 256)
            out[base1 + i] = sh_logits[i & (NT - 1)];
    }

    if (!has_edges) return;
    size_t base2 = (size_t)Bsz * N * NT + (size_t)b * N * N;

    if (N == 128) {
        // nr4 = 32 == warp width: one float4 per lane per row; 16 rows/warp.
        const int j0 = lane << 2;
        float4* rowp = reinterpret_cast<float4*>(out + base2)
                       + (size_t)warp * 32 + lane;
        #pragma unroll
        for (int r = 0; r < 16; r++) {
            const int i = warp + (r << 3);
            const int d = i - j0;
            float4 v;
            v.x = (d > 0) ? p : 0.f;
            v.y = (d > 1) ? p : 0.f;
            v.z = (d > 2) ? p : 0.f;
            v.w = (d > 3) ? p : 0.f;
            *rowp = v;
            rowp += 8 * 32;
        }
    } else if ((N & 3) == 0) {
        float4* e4 = reinterpret_cast<float4*>(out + base2);
        const int nr4 = N >> 2;
        for (int i = warp; i < N; i += 8) {
            float4* row = e4 + (size_t)i * nr4;
            for (int c = lane; c < nr4; c += 32) {
                int j0 = c << 2;
                float4 v;
                v.x = (j0 + 0 < i) ? p : 0.f;
                v.y = (j0 + 1 < i) ? p : 0.f;
                v.z = (j0 + 2 < i) ? p : 0.f;
                v.w = (j0 + 3 < i) ? p : 0.f;
                row[c] = v;
            }
        }
    } else {
        for (int i = warp; i < N; i += 8) {
            float* row = out + base2 + (size_t)i * N;
            for (int j = lane; j < N; j += 32)
                row[j] = (j < i) ? p : 0.f;
        }
    }
}

// ---------------------------------------------------------------------------
// Inputs (metadata order): z, num_nodes, W_z, b_z, W_node, b_node,
//                          W_e1, b_e1, W_e2, b_e2
// num_nodes sits in device memory; derive N on host from out_size.
// ---------------------------------------------------------------------------
extern "C" void kernel_launch(void* const* d_in, const int* in_sizes, int n_in,
                              void* d_out, int out_size)
{
    const float* z      = (const float*)d_in[0];
    const float* W_z    = (const float*)d_in[2];
    const float* b_z    = (const float*)d_in[3];
    const float* W_node = (const float*)d_in[4];
    const float* b_node = (const float*)d_in[5];
    const float* W_e1   = (const float*)d_in[6];
    const float* b_e1   = (const float*)d_in[7];
    const float* W_e2   = (const float*)d_in[8];
    const float* b_e2   = (const float*)d_in[9];
    float* out = (float*)d_out;

    int Bsz = in_sizes[0] / LATENT;
    long per = (long)out_size / (long)Bsz;

    double disc = (double)NT * NT + 4.0 * (double)per;
    int N = (int)((-(double)NT + sqrt(disc)) * 0.5 + 0.5);
    int has_edges = 1;
    if ((long)N * N + (long)NT * N != per) {
        N = (int)(per / NT);
        has_edges = 0;
    }

    float *gh = nullptr, *gws = nullptr, *gpp = nullptr;
    cudaGetSymbolAddress((void**)&gh,  g_h);
    cudaGetSymbolAddress((void**)&gws, g_we1s);
    cudaGetSymbolAddress((void**)&gpp, g_p);

    wsum_kernel<<<(HID * HID / 4) / 256, 256>>>(W_e1, gws, gpp, Bsz);

    dim3 grid(HID / 64, (Bsz + 63) / 64);

    // h = relu(z @ W_z + b_z) -> g_h
    gemm64<true, true, false><<<grid, 128>>>(z, W_z, b_z, gh,
                                             nullptr, nullptr,
                                             Bsz, HID, LATENT);
    // x = relu(h @ W_e1_sum + b_e1); g_p[b] += x . W_e2 (no C store)
    gemm64<true, false, true><<<grid, 128>>>(gh, gws, b_e1, nullptr,
                                             W_e2, gpp,
                                             Bsz, HID, HID);
    finalize_kernel<<<Bsz, 256>>>(gh, gpp, W_node, b_node, b_e2,
                                  out, Bsz, N, has_edges);
}